// round 2
// baseline (speedup 1.0000x reference)
#include <cuda_runtime.h>
#include <cuda_bf16.h>
#include <mma.h>

using namespace nvcuda;

// Problem constants (from reference): C=128 always; K<=512 protos.
#define C_DIM 128
#define MAX_K 512

#define BM 128
#define BN 256
#define LD 132           // padded row stride (floats) for smem tiles
#define EPS 1e-8f

// Scratch: normalized prototypes, tf32-rounded, fp32 container. 256 KB.
__device__ float g_protoN[MAX_K * C_DIM];

// ---------------------------------------------------------------------------
// Kernel 1: normalize prototypes (one warp per row), write tf32-rounded values
// ---------------------------------------------------------------------------
__global__ void proto_norm_kernel(const float* __restrict__ P, int K) {
    int warp = (blockIdx.x * blockDim.x + threadIdx.x) >> 5;
    int lane = threadIdx.x & 31;
    if (warp >= K) return;
    const float4* row = reinterpret_cast<const float4*>(P + (size_t)warp * C_DIM);
    float4 v = row[lane];                       // 32 lanes * float4 = 128 floats
    float s = v.x * v.x + v.y * v.y + v.z * v.z + v.w * v.w;
#pragma unroll
    for (int o = 16; o; o >>= 1) s += __shfl_xor_sync(0xFFFFFFFFu, s, o);
    float inv = 1.0f / fmaxf(sqrtf(s), EPS);
    float4 o4;
    o4.x = wmma::__float_to_tf32(v.x * inv);
    o4.y = wmma::__float_to_tf32(v.y * inv);
    o4.z = wmma::__float_to_tf32(v.z * inv);
    o4.w = wmma::__float_to_tf32(v.w * inv);
    reinterpret_cast<float4*>(g_protoN + (size_t)warp * C_DIM)[lane] = o4;
}

// ---------------------------------------------------------------------------
// Kernel 2: fused normalize(E) + tf32 GEMM + epilogue  score = -(1-cos)^2
//   CTA tile: BM=128 rows x BN=256 cols, full K depth (C=128) in one pass.
//   8 warps, each computing a 64x64 warp tile via wmma m16n16k8 tf32.
// ---------------------------------------------------------------------------
__global__ __launch_bounds__(256, 1)
void hsproto_gemm_kernel(const float* __restrict__ E,
                         float* __restrict__ out, int Kout) {
    extern __shared__ float sm[];
    float* As   = sm;                       // BM x LD
    float* Bs   = sm + BM * LD;             // BN x LD
    float* invn = Bs + BN * LD;             // BM

    const int tid = threadIdx.x;
    const size_t rowBase = (size_t)blockIdx.y * BM;
    const int    colBase = blockIdx.x * BN;

    // ---- load A tile (raw fp32 embeddings), 128x128 ----
    const float4* gA = reinterpret_cast<const float4*>(E + rowBase * C_DIM);
#pragma unroll 4
    for (int i = tid; i < BM * 32; i += 256) {
        int r = i >> 5, c = i & 31;
        *reinterpret_cast<float4*>(&As[r * LD + c * 4]) = gA[i];
    }
    // ---- load B tile (pre-normalized tf32 protos), 256x128 ----
    const float4* gB = reinterpret_cast<const float4*>(g_protoN + (size_t)colBase * C_DIM);
#pragma unroll 4
    for (int i = tid; i < BN * 32; i += 256) {
        int r = i >> 5, c = i & 31;
        *reinterpret_cast<float4*>(&Bs[r * LD + c * 4]) = gB[i];
    }
    __syncthreads();

    // ---- row norms of A (threads 0..127, one row each) ----
    if (tid < BM) {
        float s = 0.0f;
#pragma unroll
        for (int c = 0; c < 32; c++) {
            float4 v = *reinterpret_cast<float4*>(&As[tid * LD + c * 4]);
            s += v.x * v.x + v.y * v.y + v.z * v.z + v.w * v.w;
        }
        invn[tid] = 1.0f / fmaxf(sqrtf(s), EPS);
    }
    __syncthreads();

    // ---- scale A by inv-norm and round to tf32 in place ----
#pragma unroll 4
    for (int i = tid; i < BM * 32; i += 256) {
        int r = i >> 5, c = i & 31;
        float inv = invn[r];
        float4 v = *reinterpret_cast<float4*>(&As[r * LD + c * 4]);
        v.x = wmma::__float_to_tf32(v.x * inv);
        v.y = wmma::__float_to_tf32(v.y * inv);
        v.z = wmma::__float_to_tf32(v.z * inv);
        v.w = wmma::__float_to_tf32(v.w * inv);
        *reinterpret_cast<float4*>(&As[r * LD + c * 4]) = v;
    }
    __syncthreads();

    // ---- tensor-core GEMM: warp tile 64x64, 4x4 wmma fragments ----
    const int warpId = tid >> 5;
    const int wm = warpId >> 2;      // 0..1  -> row offset wm*64
    const int wn = warpId & 3;       // 0..3  -> col offset wn*64

    wmma::fragment<wmma::accumulator, 16, 16, 8, float> acc[4][4];
#pragma unroll
    for (int i = 0; i < 4; i++)
#pragma unroll
        for (int j = 0; j < 4; j++)
            wmma::fill_fragment(acc[i][j], 0.0f);

#pragma unroll
    for (int kk = 0; kk < C_DIM; kk += 8) {
        wmma::fragment<wmma::matrix_a, 16, 16, 8, wmma::precision::tf32, wmma::row_major> a[4];
        wmma::fragment<wmma::matrix_b, 16, 16, 8, wmma::precision::tf32, wmma::col_major> b[4];
#pragma unroll
        for (int i = 0; i < 4; i++)
            wmma::load_matrix_sync(a[i], &As[(wm * 64 + i * 16) * LD + kk], LD);
#pragma unroll
        for (int j = 0; j < 4; j++)
            wmma::load_matrix_sync(b[j], &Bs[(wn * 64 + j * 16) * LD + kk], LD);
#pragma unroll
        for (int i = 0; i < 4; i++)
#pragma unroll
            for (int j = 0; j < 4; j++)
                wmma::mma_sync(acc[i][j], a[i], b[j], acc[i][j]);
    }

    // ---- epilogue -(1-cos)^2 on registers, store straight to GMEM ----
    float* outBase = out + rowBase * Kout + colBase;
#pragma unroll
    for (int i = 0; i < 4; i++) {
#pragma unroll
        for (int j = 0; j < 4; j++) {
#pragma unroll
            for (int e = 0; e < acc[i][j].num_elements; e++) {
                float d = 1.0f - acc[i][j].x[e];
                acc[i][j].x[e] = -(d * d);
            }
            wmma::store_matrix_sync(outBase + (size_t)(wm * 64 + i * 16) * Kout
                                            + (wn * 64 + j * 16),
                                    acc[i][j], Kout, wmma::mem_row_major);
        }
    }
}

// ---------------------------------------------------------------------------
extern "C" void kernel_launch(void* const* d_in, const int* in_sizes, int n_in,
                              void* d_out, int out_size) {
    const float* E = (const float*)d_in[0];
    const float* P = (const float*)d_in[1];
    float* out = (float*)d_out;

    const int N = in_sizes[0] / C_DIM;   // 131072
    const int K = in_sizes[1] / C_DIM;   // 512

    // Kernel 1: normalize prototypes (K warps)
    int totalThreads = K * 32;
    proto_norm_kernel<<<(totalThreads + 255) / 256, 256>>>(P, K);

    // Kernel 2: fused GEMM
    const int smemBytes = (BM * LD + BN * LD + BM) * (int)sizeof(float);
    cudaFuncSetAttribute(hsproto_gemm_kernel,
                         cudaFuncAttributeMaxDynamicSharedMemorySize, smemBytes);
    dim3 grid(K / BN, N / BM);
    hsproto_gemm_kernel<<<grid, 256, smemBytes>>>(E, out, K);
}

// round 6
// speedup vs baseline: 2.3734x; 2.3734x over previous
#include <cuda_runtime.h>
#include <cuda_fp16.h>
#include <mma.h>
#include <cstdint>

using namespace nvcuda;

// ======================= problem constants =======================
#define C_DIM 128
#define MAX_K 512
#define BM 128
#define BN 256
#define EPS 1e-8f

// ======================= smem layout (bytes) =======================
#define LDA_RAW 132                 // fp32 A staging row stride (floats)
#define LDH     136                 // fp16 tile row stride (halves), mult of 8
#define SM_A_RAW 0                                  // 128*132*4 = 67584
#define SM_AH    (128 * LDA_RAW * 4)                // 67584; 128*136*2 = 34816
#define SM_B     (SM_AH + 128 * LDH * 2)            // 102400; 256*136*2 = 69632
#define SM_NRM   (SM_B + 256 * LDH * 2)             // 172032; 256*4 = 1024
#define SMEM_TOTAL (SM_NRM + 1024)                  // 173056

// Scratch: normalized prototypes as fp16. 128 KB.
__device__ __half g_protoH[MAX_K * C_DIM];

// ======================= helpers =======================
__device__ __forceinline__ uint32_t s2u(const void* p) {
    uint32_t a;
    asm("{ .reg .u64 t; cvta.to.shared.u64 t, %1; cvt.u32.u64 %0, t; }" : "=r"(a) : "l"(p));
    return a;
}
__device__ __forceinline__ void cp_async16(uint32_t dst, const void* src) {
    asm volatile("cp.async.cg.shared.global [%0], [%1], 16;" :: "r"(dst), "l"(src));
}
#define CP_COMMIT() asm volatile("cp.async.commit_group;" ::: "memory")
#define CP_WAIT0()  asm volatile("cp.async.wait_group 0;"  ::: "memory")

__device__ __forceinline__ uint32_t h2u(__half2 h) {
    uint32_t u;
    asm("mov.b32 %0, %1;" : "=r"(u) : "r"(*reinterpret_cast<uint32_t*>(&h)));
    return u;
}

// ======================= kernel 1: proto normalize -> fp16 =======================
__global__ void proto_norm_kernel(const float* __restrict__ P, int K) {
    int warp = (blockIdx.x * blockDim.x + threadIdx.x) >> 5;
    int lane = threadIdx.x & 31;
    if (warp >= K) return;
    const float4* row = reinterpret_cast<const float4*>(P + (size_t)warp * C_DIM);
    float4 v = row[lane];
    float s = v.x * v.x + v.y * v.y + v.z * v.z + v.w * v.w;
#pragma unroll
    for (int o = 16; o; o >>= 1) s += __shfl_xor_sync(0xFFFFFFFFu, s, o);
    float inv = 1.0f / fmaxf(sqrtf(s), EPS);
    __half2 h0 = __floats2half2_rn(v.x * inv, v.y * inv);
    __half2 h1 = __floats2half2_rn(v.z * inv, v.w * inv);
    reinterpret_cast<__half2*>(g_protoH + (size_t)warp * C_DIM)[lane * 2 + 0] = h0;
    reinterpret_cast<__half2*>(g_protoH + (size_t)warp * C_DIM)[lane * 2 + 1] = h1;
}

// ======================= kernel 2: persistent fused fp16 GEMM =======================
// grid = (K/BN, STRIDE). Each CTA: fixed column tile, loops row tiles rt += STRIDE.
// Per iter: norm+convert A(rt) [fp32->fp16] -> prefetch A(rt+STRIDE) via cp.async
//           -> wmma fp16 MMA -> epilogue -(1-cos)^2 -> store.
__global__ __launch_bounds__(256, 1)
void hsproto_gemm_kernel(const float* __restrict__ E, float* __restrict__ out,
                         int nRowTiles, int Kout) {
    extern __shared__ char smem[];
    const uint32_t sb = s2u(smem);
    float*  A_raw = reinterpret_cast<float*>(smem + SM_A_RAW);
    __half* A_h   = reinterpret_cast<__half*>(smem + SM_AH);
    __half* B_h   = reinterpret_cast<__half*>(smem + SM_B);
    float*  nrm   = reinterpret_cast<float*>(smem + SM_NRM);

    const int tid = threadIdx.x;
    const int colBase = blockIdx.x * BN;
    const int STRIDE = gridDim.y;

    // per-thread A staging mapping: half a row each
    const int r = tid >> 1;          // 0..127
    const int h = tid & 1;           // half: 0 or 1 (64 floats)
    const uint32_t aRawDst = sb + SM_A_RAW + (uint32_t)(r * LDA_RAW + h * 64) * 4;

    // ---- prologue: async-load B tile (fp16, row tid) + first A tile ----
    {
        const __half* gB = g_protoH + (size_t)(colBase + tid) * C_DIM;
        uint32_t bDst = sb + SM_B + (uint32_t)tid * (LDH * 2);
#pragma unroll
        for (int j = 0; j < 16; j++) cp_async16(bDst + j * 16, gB + j * 8);

        const float* gA = E + ((size_t)blockIdx.y * BM + r) * C_DIM + h * 64;
#pragma unroll
        for (int j = 0; j < 16; j++) cp_async16(aRawDst + j * 16, gA + j * 4);
        CP_COMMIT();
        CP_WAIT0();
    }

    const int warpId = tid >> 5;
    const int wm = warpId >> 2;      // 0..1 -> row offset wm*64
    const int wn = warpId & 3;       // 0..3 -> col offset wn*64

    for (int rt = blockIdx.y; rt < nRowTiles; rt += STRIDE) {
        // ---- row norms of A_raw (fp32): each thread sums its 64 floats ----
        float s = 0.0f;
        const float* myRaw = A_raw + r * LDA_RAW + h * 64;
#pragma unroll
        for (int j = 0; j < 16; j++) {
            float4 v = reinterpret_cast<const float4*>(myRaw)[j];
            s += v.x * v.x + v.y * v.y + v.z * v.z + v.w * v.w;
        }
        nrm[tid] = s;
        __syncthreads();                                   // sync1
        float inv = 1.0f / fmaxf(sqrtf(nrm[r * 2] + nrm[r * 2 + 1]), EPS);

        // ---- scale + convert to fp16 into A_h ----
        __half* myH = A_h + r * LDH + h * 64;
#pragma unroll
        for (int j = 0; j < 8; j++) {
            float4 v0 = reinterpret_cast<const float4*>(myRaw)[j * 2 + 0];
            float4 v1 = reinterpret_cast<const float4*>(myRaw)[j * 2 + 1];
            __half2 p0 = __floats2half2_rn(v0.x * inv, v0.y * inv);
            __half2 p1 = __floats2half2_rn(v0.z * inv, v0.w * inv);
            __half2 p2 = __floats2half2_rn(v1.x * inv, v1.y * inv);
            __half2 p3 = __floats2half2_rn(v1.z * inv, v1.w * inv);
            uint4 pk;
            pk.x = h2u(p0); pk.y = h2u(p1);
            pk.z = h2u(p2); pk.w = h2u(p3);
            reinterpret_cast<uint4*>(myH)[j] = pk;
        }
        __syncthreads();                                   // sync2: A_h/B visible, A_raw free

        // ---- prefetch next A tile (overlaps MMA + epilogue) ----
        int nrt = rt + STRIDE;
        if (nrt < nRowTiles) {
            const float* gA = E + ((size_t)nrt * BM + r) * C_DIM + h * 64;
#pragma unroll
            for (int j = 0; j < 16; j++) cp_async16(aRawDst + j * 16, gA + j * 4);
            CP_COMMIT();
        }

        // ---- fp16 tensor-core GEMM: warp tile 64x64, 4x4 m16n16k16 ----
        wmma::fragment<wmma::accumulator, 16, 16, 16, float> acc[4][4];
#pragma unroll
        for (int i = 0; i < 4; i++)
#pragma unroll
            for (int j = 0; j < 4; j++) wmma::fill_fragment(acc[i][j], 0.0f);

#pragma unroll
        for (int kk = 0; kk < C_DIM; kk += 16) {
            wmma::fragment<wmma::matrix_a, 16, 16, 16, __half, wmma::row_major> a[4];
            wmma::fragment<wmma::matrix_b, 16, 16, 16, __half, wmma::col_major> b[4];
#pragma unroll
            for (int i = 0; i < 4; i++)
                wmma::load_matrix_sync(a[i], A_h + (wm * 64 + i * 16) * LDH + kk, LDH);
#pragma unroll
            for (int j = 0; j < 4; j++)
                wmma::load_matrix_sync(b[j], B_h + (wn * 64 + j * 16) * LDH + kk, LDH);
#pragma unroll
            for (int i = 0; i < 4; i++)
#pragma unroll
                for (int j = 0; j < 4; j++)
                    wmma::mma_sync(acc[i][j], a[i], b[j], acc[i][j]);
        }

        // ---- epilogue: -(1-cos)^2 in regs, store straight to GMEM ----
        float* outBase = out + ((size_t)rt * BM) * Kout + colBase;
#pragma unroll
        for (int i = 0; i < 4; i++) {
#pragma unroll
            for (int j = 0; j < 4; j++) {
#pragma unroll
                for (int e = 0; e < acc[i][j].num_elements; e++) {
                    float d = 1.0f - acc[i][j].x[e];
                    acc[i][j].x[e] = -(d * d);
                }
                wmma::store_matrix_sync(outBase + (size_t)(wm * 64 + i * 16) * Kout
                                                + (wn * 64 + j * 16),
                                        acc[i][j], Kout, wmma::mem_row_major);
            }
        }

        CP_WAIT0();   // next A_raw resident before top-of-loop reads
    }
}

// ======================= launcher =======================
extern "C" void kernel_launch(void* const* d_in, const int* in_sizes, int n_in,
                              void* d_out, int out_size) {
    const float* E = (const float*)d_in[0];
    const float* P = (const float*)d_in[1];
    float* out = (float*)d_out;

    const int N = in_sizes[0] / C_DIM;   // 131072
    const int K = in_sizes[1] / C_DIM;   // 512

    proto_norm_kernel<<<(K * 32 + 255) / 256, 256>>>(P, K);

    static int sms = 0;
    if (!sms) {
        cudaDeviceGetAttribute(&sms, cudaDevAttrMultiProcessorCount, 0);
        cudaFuncSetAttribute(hsproto_gemm_kernel,
                             cudaFuncAttributeMaxDynamicSharedMemorySize, SMEM_TOTAL);
    }
    const int nColTiles = K / BN;                 // 2
    int stripe = sms / nColTiles;                 // persistent CTAs per column
    if (stripe < 1) stripe = 1;
    const int nRowTiles = N / BM;                 // 1024
    if (stripe > nRowTiles) stripe = nRowTiles;

    dim3 grid(nColTiles, stripe);
    hsproto_gemm_kernel<<<grid, 256, SMEM_TOTAL>>>(E, out, nRowTiles, K);
}